// round 9
// baseline (speedup 1.0000x reference)
#include <cuda_runtime.h>

#define FP      80
#define MTAPS   24
#define NSTAGES 20
#define BATCH   8
#define NFRAMES 1024
#define TLEN    (NFRAMES * FP)        // 81920

#define RPT     8                     // 8 | 80 -> thread never crosses a frame
#define BLOCK   640                   // 20 warps, one wave: grid 144
#define NWARP   (BLOCK / 32)
#define WINW    (BLOCK * RPT)         // 5120
#define HALO    (NSTAGES * MTAPS)     // 480
#define TBOUT   (WINW - HALO)         // 4640
#define BPB     ((TLEN + TBOUT - 1) / TBOUT)   // 18 -> grid 144 = one wave

typedef unsigned long long u64p;

__device__ __forceinline__ u64p pk2(float lo, float hi) {
    u64p r; asm("mov.b64 %0, {%1, %2};" : "=l"(r) : "f"(lo), "f"(hi)); return r;
}
__device__ __forceinline__ void upk2(u64p v, float& lo, float& hi) {
    asm("mov.b64 {%0, %1}, %2;" : "=f"(lo), "=f"(hi) : "l"(v));
}
__device__ __forceinline__ u64p ffma2(u64p a, u64p b, u64p c) {
    u64p d; asm("fma.rn.f32x2 %0, %1, %2, %3;" : "=l"(d) : "l"(a), "l"(b), "l"(c)); return d;
}
__device__ __forceinline__ u64p dup2(float v) { return pk2(v, v); }

__global__ void __launch_bounds__(BLOCK, 1)
fir_taylor_kernel(const float* __restrict__ x,
                  const float* __restrict__ mc,
                  const float* __restrict__ a,
                  const float* __restrict__ wts,
                  float* __restrict__ out)
{
    // Tiny double-buffered warp-boundary mailbox: row w = last 24 samples of warp w-1
    __shared__ float bnd[2][NWARP + 1][MTAPS];
    __shared__ float s_f[NSTAGES + 1];   // a[i] * prod_{k<=i} wts[k]

    const int tid  = threadIdx.x;
    const int wid  = tid >> 5;
    const int lane = tid & 31;
    const int blk  = blockIdx.x;
    const int b    = blk / BPB;
    const int tb   = blk % BPB;
    const int t0   = tb * TBOUT;
    const int g0   = t0 - HALO;

    if (tid == 0) {
        float P = 1.0f;
        s_f[0] = a[0];
        for (int i = 1; i <= NSTAGES; i++) { P *= wts[i]; s_f[i] = a[i] * P; }
    }
    // zero warp-0 mailbox rows (left-edge garbage region; must be finite)
    if (tid < MTAPS) { bnd[0][0][tid] = 0.0f; bnd[1][0][tid] = 0.0f; }

    const int lp    = tid * RPT;
    const int tbase = g0 + lp;

    // own 8 samples -> regs
    const float* xb = x + b * TLEN;
    float acc[RPT];
#pragma unroll
    for (int r = 0; r < RPT; r++) {
        int t = tbase + r;
        acc[r] = (t >= 0 && t < TLEN) ? __ldg(xb + t) : 0.0f;
    }

    // ---- stage-invariant packed coefficients kj = (cc_j, dp_j) ----
    int tc = tbase < 0 ? 0 : (tbase >= TLEN ? TLEN - 1 : tbase);
    int n  = tc / FP;
    int n1 = (n + 1 < NFRAMES) ? n + 1 : NFRAMES - 1;
    const float invP = 1.0f / (float)FP;
    const float w0   = (float)(tc - n * FP) * invP;

    const float* mrow0 = mc + ((long)b * NFRAMES + n)  * (MTAPS + 1);
    const float* mrow1 = mc + ((long)b * NFRAMES + n1) * (MTAPS + 1);

    u64p kj[MTAPS];
#pragma unroll
    for (int j = 0; j < MTAPS; j++) {
        float c0v = mrow0[j + 1];
        float d   = mrow1[j + 1] - c0v;
        kj[j] = pk2(fmaf(w0, d, c0v), d * invP);
    }
    const float k0 = mrow0[0];
    const float dk = mrow1[0] - k0;

    __syncthreads();   // covers s_f + mailbox zero init

    float y[RPT];
    {
        const float f0 = s_f[0];
#pragma unroll
        for (int r = 0; r < RPT; r++) y[r] = acc[r] * f0;
    }

#pragma unroll 1
    for (int i = 1; i <= NSTAGES; i++) {
        const float fi = s_f[i];
        const int   pb = i & 1;

        // publish warp boundary: lanes 29..31 write their 8 outputs
        if (lane >= 29) {
            float4* s = (float4*)&bnd[pb][wid + 1][(lane - 29) * 8];
            float4 f0; f0.x = acc[0]; f0.y = acc[1]; f0.z = acc[2]; f0.w = acc[3];
            float4 f1; f1.x = acc[4]; f1.y = acc[5]; f1.z = acc[6]; f1.w = acc[7];
            s[0] = f0; s[1] = f1;
        }
        __syncthreads();

        // halo w[0..23] = values at lp-24 .. lp-1, via intra-warp shuffle
        float w[MTAPS];
#pragma unroll
        for (int r = 0; r < RPT; r++) {
            w[16 + r] = __shfl_up_sync(0xFFFFFFFFu, acc[r], 1);
            w[8 + r]  = __shfl_up_sync(0xFFFFFFFFu, acc[r], 2);
            w[r]      = __shfl_up_sync(0xFFFFFFFFu, acc[r], 3);
        }
        if (lane < 3) {   // first 3 lanes: fill invalid entries from mailbox
            const float* bp = &bnd[pb][wid][0];
            const int cnt = (3 - lane) * 8;
#pragma unroll
            for (int k = 0; k < MTAPS; k++)
                if (k < cnt) w[k] = bp[lane * 8 + k];
        }

        float na[RPT];

        // ---- group A: outputs r = 0..3 (window w[24..27] = acc[0..3])
        {
            u64p ab0 = 0ULL, ab1 = 0ULL, ab2 = 0ULL, ab3 = 0ULL;
            u64p d0 = dup2(w[23]);
            u64p d1 = dup2(acc[0]);
            u64p d2 = dup2(acc[1]);
            u64p d3 = dup2(acc[2]);
#pragma unroll
            for (int j = 1; j <= MTAPS; j++) {
                u64p k = kj[j - 1];
                ab0 = ffma2(d0, k, ab0);
                ab1 = ffma2(d1, k, ab1);
                ab2 = ffma2(d2, k, ab2);
                ab3 = ffma2(d3, k, ab3);
                d3 = d2; d2 = d1; d1 = d0;
                if (j < MTAPS) d0 = dup2(w[23 - j]);
            }
            float A, B;
            upk2(ab0, A, B); na[0] = A;
            upk2(ab1, A, B); na[1] = fmaf(1.0f, B, A);
            upk2(ab2, A, B); na[2] = fmaf(2.0f, B, A);
            upk2(ab3, A, B); na[3] = fmaf(3.0f, B, A);
        }

        // ---- group B: outputs r = 4..7 (window base 28)
        {
            u64p ab0 = 0ULL, ab1 = 0ULL, ab2 = 0ULL, ab3 = 0ULL;
            u64p d0 = dup2(acc[3]);   // idx 27
            u64p d1 = dup2(acc[4]);
            u64p d2 = dup2(acc[5]);
            u64p d3 = dup2(acc[6]);
#pragma unroll
            for (int j = 1; j <= MTAPS; j++) {
                u64p k = kj[j - 1];
                ab0 = ffma2(d0, k, ab0);
                ab1 = ffma2(d1, k, ab1);
                ab2 = ffma2(d2, k, ab2);
                ab3 = ffma2(d3, k, ab3);
                d3 = d2; d2 = d1; d1 = d0;
                if (j < MTAPS) {
                    int idx = 27 - j;
                    d0 = (idx >= 24) ? dup2(acc[idx - 24]) : dup2(w[idx]);
                }
            }
            float A, B;
            upk2(ab0, A, B); na[4] = fmaf(4.0f, B, A);
            upk2(ab1, A, B); na[5] = fmaf(5.0f, B, A);
            upk2(ab2, A, B); na[6] = fmaf(6.0f, B, A);
            upk2(ab3, A, B); na[7] = fmaf(7.0f, B, A);
        }

#pragma unroll
        for (int r = 0; r < RPT; r++) {
            acc[r] = na[r];
            y[r]   = fmaf(na[r], fi, y[r]);
        }
    }

    // ---- epilogue: out = y * exp(interp(mc[...,0])) ----
    if (lp >= HALO) {
        float* ob = out + b * TLEN;
#pragma unroll
        for (int r = 0; r < RPT; r++) {
            int tt = tbase + r;
            if (tt < TLEN) {
                float K = expf(fmaf(fmaf((float)r, invP, w0), dk, k0));
                ob[tt] = y[r] * K;
            }
        }
    }
}

extern "C" void kernel_launch(void* const* d_in, const int* in_sizes, int n_in,
                              void* d_out, int out_size)
{
    (void)in_sizes; (void)n_in; (void)out_size;
    const float* x   = (const float*)d_in[0];
    const float* mc  = (const float*)d_in[1];
    const float* a   = (const float*)d_in[2];
    const float* wts = (const float*)d_in[3];
    float* out = (float*)d_out;

    fir_taylor_kernel<<<BATCH * BPB, BLOCK>>>(x, mc, a, wts, out);
}

// round 10
// speedup vs baseline: 1.1053x; 1.1053x over previous
#include <cuda_runtime.h>

#define FP      80
#define MTAPS   24
#define NSTAGES 20
#define BATCH   8
#define NFRAMES 1024
#define TLEN    (NFRAMES * FP)        // 81920

#define RPT     8                     // 8 | 80 -> thread never crosses a frame
#define BLOCK   640                   // 20 warps, grid 144 = one wave
#define NWARP   (BLOCK / 32)          // 20
#define WINW    (BLOCK * RPT)         // 5120
#define HALO    (NSTAGES * MTAPS)     // 480
#define TBOUT   (WINW - HALO)         // 4640
#define BPB     ((TLEN + TBOUT - 1) / TBOUT)   // 18
#define ROWF    (32 * RPT)            // 256 floats per warp strip row

typedef unsigned long long u64p;

__device__ __forceinline__ u64p pk2(float lo, float hi) {
    u64p r; asm("mov.b64 %0, {%1, %2};" : "=l"(r) : "f"(lo), "f"(hi)); return r;
}
__device__ __forceinline__ void upk2(u64p v, float& lo, float& hi) {
    asm("mov.b64 {%0, %1}, %2;" : "=f"(lo), "=f"(hi) : "l"(v));
}
__device__ __forceinline__ u64p ffma2(u64p a, u64p b, u64p c) {
    u64p d; asm("fma.rn.f32x2 %0, %1, %2, %3;" : "=l"(d) : "l"(a), "l"(b), "l"(c)); return d;
}
__device__ __forceinline__ u64p dup2(float v) { return pk2(v, v); }

__global__ void __launch_bounds__(BLOCK, 1)
fir_taylor_kernel(const float* __restrict__ x,
                  const float* __restrict__ mc,
                  const float* __restrict__ a,
                  const float* __restrict__ wts,
                  float* __restrict__ out)
{
    // Double-buffered per-warp state strips. Row 0 = permanent zeros (left edge).
    // Row w+1 = warp w's 256 samples. Flat: sample p of block window -> ROWF + p.
    __shared__ float strip0[(NWARP + 1) * ROWF];
    __shared__ float strip1[(NWARP + 1) * ROWF];
    __shared__ float s_f[NSTAGES + 1];          // a[i] * prod_{k<=i} wts[k]
    __shared__ volatile int wf[NWARP];          // last state index published by warp w
    __shared__ volatile int rf[NWARP + 1];      // last producer-state consumed by warp w

    const int tid  = threadIdx.x;
    const int wid  = tid >> 5;
    const int lane = tid & 31;
    const int blk  = blockIdx.x;
    const int b    = blk / BPB;
    const int tb   = blk % BPB;
    const int t0   = tb * TBOUT;
    const int g0   = t0 - HALO;

    if (tid == 0) {
        float P = 1.0f;
        s_f[0] = a[0];
        for (int i = 1; i <= NSTAGES; i++) { P *= wts[i]; s_f[i] = a[i] * P; }
    }
    if (tid < NWARP) { wf[tid] = 0; rf[tid] = -1; }     // state_0 published below
    if (tid == 0)    { rf[NWARP] = 0x7FFFFFFF; }
    if (tid < ROWF)  { strip0[tid] = 0.0f; strip1[tid] = 0.0f; }  // zero left row

    const int lp    = tid * RPT;
    const int tbase = g0 + lp;

    // own 8 samples -> regs, publish state_0 into strip0
    const float* xb = x + b * TLEN;
    float acc[RPT];
#pragma unroll
    for (int r = 0; r < RPT; r++) {
        int t = tbase + r;
        acc[r] = (t >= 0 && t < TLEN) ? __ldg(xb + t) : 0.0f;
    }
    {
        float4* st = (float4*)(strip0 + ROWF + lp);
        float4 f0; f0.x = acc[0]; f0.y = acc[1]; f0.z = acc[2]; f0.w = acc[3];
        float4 f1; f1.x = acc[4]; f1.y = acc[5]; f1.z = acc[6]; f1.w = acc[7];
        st[0] = f0; st[1] = f1;
    }

    // ---- stage-invariant packed coefficients kj = (cc_j, dp_j) ----
    int tc = tbase < 0 ? 0 : (tbase >= TLEN ? TLEN - 1 : tbase);
    int n  = tc / FP;
    int n1 = (n + 1 < NFRAMES) ? n + 1 : NFRAMES - 1;
    const float invP = 1.0f / (float)FP;
    const float w0   = (float)(tc - n * FP) * invP;

    const float* mrow0 = mc + ((long)b * NFRAMES + n)  * (MTAPS + 1);
    const float* mrow1 = mc + ((long)b * NFRAMES + n1) * (MTAPS + 1);

    u64p kj[MTAPS];
#pragma unroll
    for (int j = 0; j < MTAPS; j++) {
        float c0v = mrow0[j + 1];
        float d   = mrow1[j + 1] - c0v;
        kj[j] = pk2(fmaf(w0, d, c0v), d * invP);
    }
    const float k0 = mrow0[0];
    const float dk = mrow1[0] - k0;

    __syncthreads();   // covers s_f, flags, zero row, state_0 strips. ONLY block barrier.

    float y[RPT];
    {
        const float f0 = s_f[0];
#pragma unroll
        for (int r = 0; r < RPT; r++) y[r] = acc[r] * f0;
    }

#pragma unroll 1
    for (int i = 1; i <= NSTAGES; i++) {
        const float fi = s_f[i];
        float* curb = ((i - 1) & 1) ? strip1 : strip0;

        // wait for producer warp's state_{i-1}
        if (wid > 0) { while (wf[wid - 1] < i - 1) { } }
        __threadfence_block();

        // halo w[0..23] = state_{i-1} at positions lp-24..lp-1  (flat: ROWF+lp-24)
        float w[MTAPS];
        {
            const float4* v = (const float4*)(curb + (ROWF - MTAPS) + lp);
#pragma unroll
            for (int q = 0; q < MTAPS / 4; q++) {
                float4 f = v[q];
                w[4*q+0] = f.x; w[4*q+1] = f.y; w[4*q+2] = f.z; w[4*q+3] = f.w;
            }
        }
        __threadfence_block();
        if (wid > 0 && lane == 0) rf[wid] = i - 1;   // release producer's buffer

        float na[RPT];

        // ---- group A: outputs r = 0..3 (window w[24..27] = acc[0..3])
        {
            u64p ab0 = 0ULL, ab1 = 0ULL, ab2 = 0ULL, ab3 = 0ULL;
            u64p d0 = dup2(w[23]);
            u64p d1 = dup2(acc[0]);
            u64p d2 = dup2(acc[1]);
            u64p d3 = dup2(acc[2]);
#pragma unroll
            for (int j = 1; j <= MTAPS; j++) {
                u64p k = kj[j - 1];
                ab0 = ffma2(d0, k, ab0);
                ab1 = ffma2(d1, k, ab1);
                ab2 = ffma2(d2, k, ab2);
                ab3 = ffma2(d3, k, ab3);
                d3 = d2; d2 = d1; d1 = d0;
                if (j < MTAPS) d0 = dup2(w[23 - j]);
            }
            float A, B;
            upk2(ab0, A, B); na[0] = A;
            upk2(ab1, A, B); na[1] = fmaf(1.0f, B, A);
            upk2(ab2, A, B); na[2] = fmaf(2.0f, B, A);
            upk2(ab3, A, B); na[3] = fmaf(3.0f, B, A);
        }

        // ---- group B: outputs r = 4..7 (window base 28)
        {
            u64p ab0 = 0ULL, ab1 = 0ULL, ab2 = 0ULL, ab3 = 0ULL;
            u64p d0 = dup2(acc[3]);   // idx 27
            u64p d1 = dup2(acc[4]);
            u64p d2 = dup2(acc[5]);
            u64p d3 = dup2(acc[6]);
#pragma unroll
            for (int j = 1; j <= MTAPS; j++) {
                u64p k = kj[j - 1];
                ab0 = ffma2(d0, k, ab0);
                ab1 = ffma2(d1, k, ab1);
                ab2 = ffma2(d2, k, ab2);
                ab3 = ffma2(d3, k, ab3);
                d3 = d2; d2 = d1; d1 = d0;
                if (j < MTAPS) {
                    int idx = 27 - j;
                    d0 = (idx >= 24) ? dup2(acc[idx - 24]) : dup2(w[idx]);
                }
            }
            float A, B;
            upk2(ab0, A, B); na[4] = fmaf(4.0f, B, A);
            upk2(ab1, A, B); na[5] = fmaf(5.0f, B, A);
            upk2(ab2, A, B); na[6] = fmaf(6.0f, B, A);
            upk2(ab3, A, B); na[7] = fmaf(7.0f, B, A);
        }

#pragma unroll
        for (int r = 0; r < RPT; r++) acc[r] = na[r];

        // publish state_i (not needed after the last stage)
        if (i < NSTAGES) {
            if (wid < NWARP - 1) { while (rf[wid + 1] < i - 2) { } }
            float* nxtb = (i & 1) ? strip1 : strip0;
            float4* st = (float4*)(nxtb + ROWF + lp);
            float4 f0; f0.x = acc[0]; f0.y = acc[1]; f0.z = acc[2]; f0.w = acc[3];
            float4 f1; f1.x = acc[4]; f1.y = acc[5]; f1.z = acc[6]; f1.w = acc[7];
            st[0] = f0; st[1] = f1;
            __syncwarp();
            __threadfence_block();
            if (lane == 0) wf[wid] = i;
        }

#pragma unroll
        for (int r = 0; r < RPT; r++) y[r] = fmaf(na[r], fi, y[r]);
    }

    // ---- epilogue: out = y * exp(interp(mc[...,0])) ----
    if (lp >= HALO) {
        float* ob = out + b * TLEN;
#pragma unroll
        for (int r = 0; r < RPT; r++) {
            int tt = tbase + r;
            if (tt < TLEN) {
                float K = expf(fmaf(fmaf((float)r, invP, w0), dk, k0));
                ob[tt] = y[r] * K;
            }
        }
    }
}

extern "C" void kernel_launch(void* const* d_in, const int* in_sizes, int n_in,
                              void* d_out, int out_size)
{
    (void)in_sizes; (void)n_in; (void)out_size;
    const float* x   = (const float*)d_in[0];
    const float* mc  = (const float*)d_in[1];
    const float* a   = (const float*)d_in[2];
    const float* wts = (const float*)d_in[3];
    float* out = (float*)d_out;

    fir_taylor_kernel<<<BATCH * BPB, BLOCK>>>(x, mc, a, wts, out);
}

// round 12
// speedup vs baseline: 1.2364x; 1.1187x over previous
#include <cuda_runtime.h>

#define FP      80
#define MTAPS   24
#define NSTAGES 20
#define BATCH   8
#define NFRAMES 1024
#define TLEN    (NFRAMES * FP)        // 81920

#define RPT     8                     // 8 | 80 -> thread never crosses a frame
#define BLOCK   640                   // 20 warps, grid 144 = one wave
#define WINW    (BLOCK * RPT)         // 5120
#define HALO    (NSTAGES * MTAPS)     // 480
#define TBOUT   (WINW - HALO)         // 4640
#define PADZ    24
#define BPB     ((TLEN + TBOUT - 1) / TBOUT)   // 18 -> grid 144 = one wave

typedef unsigned long long u64p;

__device__ __forceinline__ u64p pk2(float lo, float hi) {
    u64p r; asm("mov.b64 %0, {%1, %2};" : "=l"(r) : "f"(lo), "f"(hi)); return r;
}
__device__ __forceinline__ void upk2(u64p v, float& lo, float& hi) {
    asm("mov.b64 {%0, %1}, %2;" : "=f"(lo), "=f"(hi) : "l"(v));
}
__device__ __forceinline__ u64p ffma2(u64p a, u64p b, u64p c) {
    u64p d; asm("fma.rn.f32x2 %0, %1, %2, %3;" : "=l"(d) : "l"(a), "l"(b), "l"(c)); return d;
}
__device__ __forceinline__ u64p dup2(float v) { return pk2(v, v); }

__global__ void __launch_bounds__(BLOCK, 1)
fir_taylor_kernel(const float* __restrict__ x,
                  const float* __restrict__ mc,
                  const float* __restrict__ a,
                  const float* __restrict__ wts,
                  float* __restrict__ out)
{
    __shared__ float buf0[WINW + PADZ];
    __shared__ float buf1[WINW + PADZ];
    __shared__ float s_f[NSTAGES + 1];   // a[i] * prod_{k<=i} wts[k]

    const int tid = threadIdx.x;
    const int blk = blockIdx.x;
    const int b   = blk / BPB;
    const int tb  = blk % BPB;
    const int t0  = tb * TBOUT;
    const int g0  = t0 - HALO;

    if (tid == 0) {
        float P = 1.0f;
        s_f[0] = a[0];
        for (int i = 1; i <= NSTAGES; i++) { P *= wts[i]; s_f[i] = a[i] * P; }
    }
    if (tid < PADZ) { buf0[tid] = 0.0f; buf1[tid] = 0.0f; }

    const int lp    = tid * RPT;
    const int tbase = g0 + lp;

    // own 8 samples -> regs + smem (state 0)
    const float* xb = x + b * TLEN;
    float acc[RPT];
#pragma unroll
    for (int r = 0; r < RPT; r++) {
        int t = tbase + r;
        acc[r] = (t >= 0 && t < TLEN) ? __ldg(xb + t) : 0.0f;
    }
    {
        float4* st = (float4*)(buf0 + PADZ + lp);
        float4 f0; f0.x = acc[0]; f0.y = acc[1]; f0.z = acc[2]; f0.w = acc[3];
        float4 f1; f1.x = acc[4]; f1.y = acc[5]; f1.z = acc[6]; f1.w = acc[7];
        st[0] = f0; st[1] = f1;
    }

    // ---- stage-invariant packed coefficients kj = (cc_j, dp_j) ----
    int tc = tbase < 0 ? 0 : (tbase >= TLEN ? TLEN - 1 : tbase);
    int n  = tc / FP;
    int n1 = (n + 1 < NFRAMES) ? n + 1 : NFRAMES - 1;
    const float invP = 1.0f / (float)FP;
    const float w0   = (float)(tc - n * FP) * invP;

    const float* mrow0 = mc + ((long)b * NFRAMES + n)  * (MTAPS + 1);
    const float* mrow1 = mc + ((long)b * NFRAMES + n1) * (MTAPS + 1);

    u64p kj[MTAPS];
#pragma unroll
    for (int j = 0; j < MTAPS; j++) {
        float c0v = mrow0[j + 1];
        float d   = mrow1[j + 1] - c0v;
        kj[j] = pk2(fmaf(w0, d, c0v), d * invP);
    }
    const float k0 = mrow0[0];
    const float dk = mrow1[0] - k0;

    __syncthreads();

    // Deferred-y pipeline: y starts at 0; each stage adds PREVIOUS state * its factor
    float y[RPT];
#pragma unroll
    for (int r = 0; r < RPT; r++) y[r] = 0.0f;
    float fprev = s_f[0];

    float* cur = buf0;
    float* nxt = buf1;

#pragma unroll 1
    for (int i = 1; i <= NSTAGES; i++) {
        // (1) issue halo loads first: w[0..23] = cur[lp-24 .. lp-1]
        float w[MTAPS];
        {
            const float4* v = (const float4*)(cur + PADZ + lp - MTAPS);
#pragma unroll
            for (int q = 0; q < MTAPS / 4; q++) {
                float4 f = v[q];
                w[4*q+0] = f.x; w[4*q+1] = f.y; w[4*q+2] = f.z; w[4*q+3] = f.w;
            }
        }

        // (2) deferred y-update in the LDS shadow (independent of loads)
#pragma unroll
        for (int r = 0; r < RPT; r++) y[r] = fmaf(acc[r], fprev, y[r]);
        fprev = s_f[i];

        float na[RPT];

        // ---- group A: outputs r = 0..3 (window w[24..27] = acc[0..3])
        {
            u64p ab0 = 0ULL, ab1 = 0ULL, ab2 = 0ULL, ab3 = 0ULL;
            u64p d0 = dup2(w[23]);
            u64p d1 = dup2(acc[0]);
            u64p d2 = dup2(acc[1]);
            u64p d3 = dup2(acc[2]);
#pragma unroll
            for (int j = 1; j <= MTAPS; j++) {
                u64p k = kj[j - 1];
                ab0 = ffma2(d0, k, ab0);
                ab1 = ffma2(d1, k, ab1);
                ab2 = ffma2(d2, k, ab2);
                ab3 = ffma2(d3, k, ab3);
                d3 = d2; d2 = d1; d1 = d0;
                if (j < MTAPS) d0 = dup2(w[23 - j]);
            }
            float A, B;
            upk2(ab0, A, B); na[0] = A;
            upk2(ab1, A, B); na[1] = fmaf(1.0f, B, A);
            upk2(ab2, A, B); na[2] = fmaf(2.0f, B, A);
            upk2(ab3, A, B); na[3] = fmaf(3.0f, B, A);
        }

        // ---- group B: outputs r = 4..7 (window base 28)
        {
            u64p ab0 = 0ULL, ab1 = 0ULL, ab2 = 0ULL, ab3 = 0ULL;
            u64p d0 = dup2(acc[3]);   // idx 27
            u64p d1 = dup2(acc[4]);
            u64p d2 = dup2(acc[5]);
            u64p d3 = dup2(acc[6]);
#pragma unroll
            for (int j = 1; j <= MTAPS; j++) {
                u64p k = kj[j - 1];
                ab0 = ffma2(d0, k, ab0);
                ab1 = ffma2(d1, k, ab1);
                ab2 = ffma2(d2, k, ab2);
                ab3 = ffma2(d3, k, ab3);
                d3 = d2; d2 = d1; d1 = d0;
                if (j < MTAPS) {
                    int idx = 27 - j;
                    d0 = (idx >= 24) ? dup2(acc[idx - 24]) : dup2(w[idx]);
                }
            }
            float A, B;
            upk2(ab0, A, B); na[4] = fmaf(4.0f, B, A);
            upk2(ab1, A, B); na[5] = fmaf(5.0f, B, A);
            upk2(ab2, A, B); na[6] = fmaf(6.0f, B, A);
            upk2(ab3, A, B); na[7] = fmaf(7.0f, B, A);
        }

        // (3) publish immediately, then bookkeeping, then barrier
        if (i < NSTAGES) {
            float4* st = (float4*)(nxt + PADZ + lp);
            float4 f0; f0.x = na[0]; f0.y = na[1]; f0.z = na[2]; f0.w = na[3];
            float4 f1; f1.x = na[4]; f1.y = na[5]; f1.z = na[6]; f1.w = na[7];
            st[0] = f0; st[1] = f1;
        }

#pragma unroll
        for (int r = 0; r < RPT; r++) acc[r] = na[r];

        if (i < NSTAGES) {
            __syncthreads();
            float* tmp = cur; cur = nxt; nxt = tmp;
        }
    }

    // final deferred term: y += state_20 * f_20
#pragma unroll
    for (int r = 0; r < RPT; r++) y[r] = fmaf(acc[r], fprev, y[r]);

    // ---- epilogue: out = y * exp(interp(mc[...,0])) ----
    if (lp >= HALO) {
        float* ob = out + b * TLEN;
#pragma unroll
        for (int r = 0; r < RPT; r++) {
            int tt = tbase + r;
            if (tt < TLEN) {
                float K = expf(fmaf(fmaf((float)r, invP, w0), dk, k0));
                ob[tt] = y[r] * K;
            }
        }
    }
}

extern "C" void kernel_launch(void* const* d_in, const int* in_sizes, int n_in,
                              void* d_out, int out_size)
{
    (void)in_sizes; (void)n_in; (void)out_size;
    const float* x   = (const float*)d_in[0];
    const float* mc  = (const float*)d_in[1];
    const float* a   = (const float*)d_in[2];
    const float* wts = (const float*)d_in[3];
    float* out = (float*)d_out;

    fir_taylor_kernel<<<BATCH * BPB, BLOCK>>>(x, mc, a, wts, out);
}